// round 7
// baseline (speedup 1.0000x reference)
#include <cuda_runtime.h>
#include <math.h>

#define BB 64
#define NN 8732
#define CC 21
#define MM 16
#define BN (BB*NN)

// ---- scratch (no allocations allowed) ----
__device__ float        g_vbuf[BN];          // -log_softmax_bg per anchor (0 if assigned)
__device__ int          g_ktab[BB*MM];
__device__ int          g_ctab[BB*MM];
__device__ unsigned int g_hist1[4096];
__device__ unsigned int g_h2c[4096];
__device__ float        g_h2s[4096];
__device__ double       g_posCe;
__device__ double       g_negHi;
__device__ double       g_bboxSum;
__device__ int          g_posCnt;
__device__ int          g_validCnt;
__device__ int          g_b0;
__device__ int          g_cntAbove1;
__device__ unsigned int g_ctr1;              // block-completion counter for k_main
__device__ unsigned int g_ctr2;              // block-completion counter for k_pass2

__device__ __forceinline__ float smooth_l1(float d) {
    float a = fabsf(d);
    return a < 1.0f ? 0.5f * d * d : a - 0.5f;
}

// K_A: zero scratch + parse targets (single block, 1024 threads)
__global__ void __launch_bounds__(1024) k_prep(const float* __restrict__ target,
                                               const float* __restrict__ predBoxes,
                                               const float* __restrict__ bboxOut) {
    int tid = threadIdx.x;
#pragma unroll
    for (int j = 0; j < 4; j++) {
        int i = tid + j * 1024;
        g_hist1[i] = 0u;
        g_h2c[i]   = 0u;
        g_h2s[i]   = 0.0f;
    }
    if (tid == 0) {
        g_posCe = 0.0; g_negHi = 0.0; g_bboxSum = 0.0;
        g_posCnt = 0;  g_validCnt = 0; g_b0 = 0; g_cntAbove1 = 0;
        g_ctr1 = 0u;   g_ctr2 = 0u;
    }
    __syncthreads();   // REQUIRED: parse-phase atomics below hit the accumulators
                       // zeroed above; without this barrier tid 0's zero-stores
                       // race with other threads' atomicAdds (R5 failure).

    // parse: tid -> (b, m), exactly 64*16 = 1024
    int b = tid >> 4;
    int m = tid & 15;
    const float* t = target + b * (1 + 6 * MM);
    int num = (int)t[0];
    const float* e = t + 1 + 6 * m;
    int ci = (int)e[0];
    int k  = (int)e[5];
    bool valid = (m < num);

    g_ktab[b * MM + m] = valid ? k : -1;
    g_ctab[b * MM + m] = (valid && ci > 0) ? ci : 0;

    if (valid) {
        atomicAdd(&g_validCnt, 1);
        if (ci > 0) atomicAdd(&g_posCnt, 1);

        float tx1 = e[1], ty1 = e[2], tx2 = e[3], ty2 = e[4];
        const float* p = predBoxes + (size_t)k * 4;
        float px1 = p[0], py1 = p[1], px2 = p[2], py2 = p[3];
        float pw = px2 - px1, ph = py2 - py1;
        float eb0 = ((tx1 + tx2) * 0.5f - (px1 + px2) * 0.5f) / pw;
        float eb1 = ((ty1 + ty2) * 0.5f - (py1 + py2) * 0.5f) / ph;
        float eb2 = logf((tx2 - tx1) / pw);
        float eb3 = logf((ty2 - ty1) / ph);

        const float* bo = bboxOut + ((size_t)b * NN + (size_t)k) * 4;
        float s = smooth_l1(bo[0] - eb0) + smooth_l1(bo[1] - eb1)
                + smooth_l1(bo[2] - eb2) + smooth_l1(bo[3] - eb3);
        atomicAdd(&g_bboxSum, (double)s);
    }
}

// K_B: per-anchor log-softmax; positive CE; v-buffer + level-1 histogram.
// Last block to finish runs the level-1 boundary-bin suffix scan.
__global__ void __launch_bounds__(256) k_main(const float* __restrict__ conf) {
    __shared__ int sk[MM], sc[MM];
    __shared__ unsigned int sh[4096];
    int tid = threadIdx.x;
    int b = blockIdx.y;
    if (tid < MM) { sk[tid] = g_ktab[b * MM + tid]; sc[tid] = g_ctab[b * MM + tid]; }
    for (int i = tid; i < 4096; i += blockDim.x) sh[i] = 0u;
    __syncthreads();

    int n = blockIdx.x * blockDim.x + tid;
    if (n < NN) {
        const float* row = conf + ((size_t)b * NN + (size_t)n) * CC;
        float r[CC];
#pragma unroll
        for (int c = 0; c < CC; c++) r[c] = __ldg(row + c);
        float mx = r[0];
#pragma unroll
        for (int c = 1; c < CC; c++) mx = fmaxf(mx, r[c]);
        float se = 0.0f;
#pragma unroll
        for (int c = 0; c < CC; c++) se += __expf(r[c] - mx);
        float logZ = mx + __logf(se);

        int cls = -1;  // -1 = unassigned
#pragma unroll
        for (int m = 0; m < MM; m++)
            if (sk[m] == n) cls = sc[m];

        size_t idx = (size_t)b * NN + (size_t)n;
        if (cls < 0) {
            float v = fmaxf(logZ - r[0], 0.0f);   // -log_softmax of background, >= 0
            g_vbuf[idx] = v;
            atomicAdd(&sh[__float_as_uint(v) >> 20], 1u);
        } else {
            g_vbuf[idx] = 0.0f;                   // assigned: excluded from negatives
            if (cls > 0) {
                float x = __ldg(row + cls);
                atomicAdd(&g_posCe, (double)(logZ - x));
            }
        }
    }
    __syncthreads();
    for (int i = tid; i < 4096; i += blockDim.x) {
        unsigned int c = sh[i];
        if (c) atomicAdd(&g_hist1[i], c);
    }

    // ---- last-block tail: level-1 suffix scan ----
    __shared__ bool isLast;
    __threadfence();
    __syncthreads();
    if (tid == 0) {
        unsigned int t = atomicAdd(&g_ctr1, 1u);
        isLast = (t == gridDim.x * gridDim.y - 1);
    }
    __syncthreads();
    if (!isLast) return;

    // 256 threads, 16 bins each (chunk t = bins [16t, 16t+16))
    __shared__ unsigned int ssum[256];
    unsigned int c[16];
    unsigned int s = 0;
#pragma unroll
    for (int j = 0; j < 16; j++) {
        c[j] = __ldcg(&g_hist1[tid * 16 + j]);
        s += c[j];
    }
    ssum[tid] = s;
    __syncthreads();
    for (int off = 1; off < 256; off <<= 1) {
        unsigned int v = (tid + off < 256) ? ssum[tid + off] : 0u;
        __syncthreads();
        ssum[tid] += v;
        __syncthreads();
    }
    int K = 3 * g_posCnt;
    unsigned int e = (tid < 255) ? ssum[tid + 1] : 0u;   // suffix excl of chunk
#pragma unroll
    for (int j = 15; j >= 0; j--) {
        if ((int)e < K && (int)(e + c[j]) >= K) {
            g_b0 = tid * 16 + j;
            g_cntAbove1 = (int)e;
        }
        e += c[j];
    }
    if (tid == 0 && (int)ssum[0] < K) {   // degenerate: fewer candidates than K
        g_b0 = 0;
        g_cntAbove1 = (int)ssum[0];
    }
}

// K_C: exact sum above boundary bin; level-2 histogram of boundary bin.
// Last block to finish runs the finalize tail and writes the output.
__global__ void __launch_bounds__(256) k_pass2(float* __restrict__ out) {
    int tid = threadIdx.x;
    int i = blockIdx.x * blockDim.x + tid;
    int b0 = g_b0;
    if (i < BN) {
        float v = g_vbuf[i];
        unsigned int bits = __float_as_uint(v);
        if (bits != 0u) {
            int t12 = (int)(bits >> 20);
            if (t12 > b0) {
                atomicAdd(&g_negHi, (double)v);
            } else if (t12 == b0) {
                unsigned int b2 = (bits >> 8) & 0xFFFu;
                atomicAdd(&g_h2c[b2], 1u);
                atomicAdd(&g_h2s[b2], v);
            }
        }
    }

    // ---- last-block tail: level-2 finalize ----
    __shared__ bool isLast;
    __threadfence();
    __syncthreads();
    if (tid == 0) {
        unsigned int t = atomicAdd(&g_ctr2, 1u);
        isLast = (t == gridDim.x - 1);
    }
    __syncthreads();
    if (!isLast) return;

    __shared__ unsigned int ssum[256];
    __shared__ double sred[256];
    unsigned int c[16];
    float        bs[16];
    unsigned int s = 0;
#pragma unroll
    for (int j = 0; j < 16; j++) {
        c[j]  = __ldcg(&g_h2c[tid * 16 + j]);
        bs[j] = __ldcg(&g_h2s[tid * 16 + j]);
        s += c[j];
    }
    ssum[tid] = s;
    __syncthreads();
    for (int off = 1; off < 256; off <<= 1) {
        unsigned int v = (tid + off < 256) ? ssum[tid + off] : 0u;
        __syncthreads();
        ssum[tid] += v;
        __syncthreads();
    }

    int K = 3 * g_posCnt;
    long long r = (long long)K - (long long)g_cntAbove1;
    if (r < 0) r = 0;

    unsigned int e = (tid < 255) ? ssum[tid + 1] : 0u;
    double local = 0.0;
#pragma unroll
    for (int j = 15; j >= 0; j--) {
        unsigned int cj = c[j];
        if (cj) {
            long long rem = r - (long long)e;               // budget left at this bin
            long long take = rem < 0 ? 0 : (rem > (long long)cj ? (long long)cj : rem);
            if (take > 0)
                local += (double)bs[j] * ((double)take / (double)cj);  // take==cj -> exact
        }
        e += cj;
    }
    sred[tid] = local;
    __syncthreads();
    for (int off = 128; off > 0; off >>= 1) {
        if (tid < off) sred[tid] += sred[tid + off];
        __syncthreads();
    }

    if (tid == 0) {
        double sneg = __ldcg(&g_negHi) + sred[0];
        long long selCnt = (long long)g_posCnt + (long long)K;
        if (selCnt < 1) selCnt = 1;
        double conf_loss = (__ldcg(&g_posCe) + sneg) / (double)selCnt;
        long long denomB = 4LL * (long long)g_validCnt;
        if (denomB < 1) denomB = 1;
        double bbox_loss = __ldcg(&g_bboxSum) / (double)denomB;
        out[0] = (float)conf_loss;
        out[1] = (float)bbox_loss;
    }
}

extern "C" void kernel_launch(void* const* d_in, const int* in_sizes, int n_in,
                              void* d_out, int out_size) {
    const float* conf   = (const float*)d_in[0];   // (B, N, C)
    const float* bbox   = (const float*)d_in[1];   // (B, N, 4)
    const float* target = (const float*)d_in[2];   // (B, 1+6M)
    const float* pred   = (const float*)d_in[3];   // (N, 4)
    float* out = (float*)d_out;

    k_prep<<<1, 1024>>>(target, pred, bbox);
    dim3 g((NN + 255) / 256, BB);
    k_main<<<g, 256>>>(conf);
    k_pass2<<<(BN + 255) / 256, 256>>>(out);
}